// round 1
// baseline (speedup 1.0000x reference)
#include <cuda_runtime.h>

// dag[i,j] closed form (scan unrolled):
//   b[i,j]  = (e[i,j] + g0[i,j]) > (1 - e[i,j] + g1[i,j])
//   nr[j]   = !((rp[j] + gr0[j]) > (1 - rp[j] + gr1[j]))
//   dag[i,j] = 0                           (i == j)
//            = b[i,j]*nr[j]                (j > i)
//            = b[i,j]*nr[j]*(1-b[j,i]*nr[i]) (j < i)
//
// Block handles the tile pair {(bi,bj),(bj,bi)}, bi<=bj, so every edge
// element is read from HBM exactly once.

#define TILE 32
#define ROWS_PER_THREAD 4   // blockDim = (32, 8)

__global__ __launch_bounds__(256) void dag_pair_kernel(
    const float*  __restrict__ rootp,   // (n)
    const float*  __restrict__ edgep,   // (n, n)
    const float2* __restrict__ groot,   // (n, 2) as float2
    const float2* __restrict__ gedge,   // (n, n, 2) as float2
    float*        __restrict__ out,     // (n, n)
    int n)
{
    const int bi = blockIdx.y;
    const int bj = blockIdx.x;
    if (bj < bi) return;  // only upper-triangular tile pairs

    __shared__ float vP[TILE][TILE + 1];  // +1 pad: conflict-free transpose
    __shared__ float nrI[TILE];           // not_root for bi-tile indices
    __shared__ float nrJ[TILE];           // not_root for bj-tile indices

    const int tx = threadIdx.x;           // 0..31 (column within tile)
    const int ty = threadIdx.y;           // 0..7

    if (ty == 0) {
        int gi = bi * TILE + tx;
        float p  = rootp[gi];
        float2 g = groot[gi];
        nrI[tx] = ((p + g.x) > (1.0f - p + g.y)) ? 0.0f : 1.0f;
        int gj = bj * TILE + tx;
        p = rootp[gj];
        g = groot[gj];
        nrJ[tx] = ((p + g.x) > (1.0f - p + g.y)) ? 0.0f : 1.0f;
    }
    __syncthreads();

    // ---- Phase A: upper tile P at (bi, bj): v = b * nr[col] ----
    const int colP = bj * TILE + tx;
    #pragma unroll
    for (int r = 0; r < ROWS_PER_THREAD; r++) {
        int lr  = ty + r * 8;
        int row = bi * TILE + lr;
        long idx = (long)row * n + colP;
        float p  = edgep[idx];
        float2 g = gedge[idx];
        float b  = ((p + g.x) > (1.0f - p + g.y)) ? 1.0f : 0.0f;
        vP[lr][tx] = b * nrJ[tx];
    }
    __syncthreads();

    if (bi == bj) {
        // Diagonal tile: both triangles + zero diagonal, from smem.
        #pragma unroll
        for (int r = 0; r < ROWS_PER_THREAD; r++) {
            int lr  = ty + r * 8;
            int row = bi * TILE + lr;
            float v = vP[lr][tx];
            float o;
            if (tx > lr)      o = v;                              // j > i
            else if (tx < lr) o = v * (1.0f - vP[tx][lr]);        // j < i
            else              o = 0.0f;                           // j == i
            out[(long)row * n + colP] = o;
        }
    } else {
        // P is strictly above the diagonal: dag = v directly.
        #pragma unroll
        for (int r = 0; r < ROWS_PER_THREAD; r++) {
            int lr  = ty + r * 8;
            int row = bi * TILE + lr;
            out[(long)row * n + colP] = vP[lr][tx];
        }
        // ---- Phase B: lower tile Q at (bj, bi): dag = v_Q * (1 - vP^T) ----
        const int colQ = bi * TILE + tx;
        #pragma unroll
        for (int r = 0; r < ROWS_PER_THREAD; r++) {
            int lr  = ty + r * 8;
            int row = bj * TILE + lr;
            long idx = (long)row * n + colQ;
            float p  = edgep[idx];
            float2 g = gedge[idx];
            float b  = ((p + g.x) > (1.0f - p + g.y)) ? 1.0f : 0.0f;
            float v  = b * nrI[tx];
            out[(long)row * n + colQ] = v * (1.0f - vP[tx][lr]);
        }
    }
}

extern "C" void kernel_launch(void* const* d_in, const int* in_sizes, int n_in,
                              void* d_out, int out_size) {
    // metadata order: root_probs (n), edge_probs (n*n), g_root (n,2), g_edge (n,n,2)
    const float*  rootp = (const float*)d_in[0];
    const float*  edgep = (const float*)d_in[1];
    const float2* groot = (const float2*)d_in[2];
    const float2* gedge = (const float2*)d_in[3];
    float* out = (float*)d_out;
    int n = in_sizes[0];

    dim3 block(32, 8);
    dim3 grid(n / TILE, n / TILE);
    dag_pair_kernel<<<grid, block>>>(rootp, edgep, groot, gedge, out, n);
}

// round 2
// speedup vs baseline: 1.0331x; 1.0331x over previous
#include <cuda_runtime.h>

// dag[i,j] closed form (reference scan collapses; ST forward == hard sample):
//   b[i,j]  = (e + g0) > (1 - e + g1)
//   nr[j]   = !((rp[j] + gr0[j]) > (1 - rp[j] + gr1[j]))
//   dag[i,j] = 0                              (i == j)
//            = b[i,j]*nr[j]                   (j > i)
//            = b[i,j]*nr[j]*(1 - b[j,i]*nr[i])(j < i)
//
// Triangular grid: block `bid` owns tile pair {(bi,bj),(bj,bi)}, bi<=bj.
// All global loads for BOTH tiles are issued up front (single DRAM round,
// max MLP), then smem transpose resolves the j<i coupling.

#define TILE 32

__global__ __launch_bounds__(256) void dag_pair_kernel(
    const float*  __restrict__ rootp,   // (n)
    const float4* __restrict__ edgep4,  // (n, n/4)
    const float2* __restrict__ groot,   // (n) float2
    const float4* __restrict__ gedge4,  // (n, n/2) float4 = 2 cols
    float4*       __restrict__ out4,    // (n, n/4)
    int n, int T)                        // T = n/TILE
{
    // --- inverse triangular map: bid -> (bi, bj), bi <= bj ---
    int bid = blockIdx.x;
    float tf = (float)T + 0.5f;
    int bi = (int)(tf - sqrtf(tf * tf - 2.0f * (float)bid));
    // fixup (float sqrt can be off by one)
    while ((bi + 1) * T - ((bi + 1) * bi) / 2 <= bid) bi++;
    while (bi * T - (bi * (bi - 1)) / 2 > bid) bi--;
    int bj = bi + (bid - (bi * T - (bi * (bi - 1)) / 2));

    const int tid = threadIdx.x;
    const int lr  = tid >> 3;          // 0..31  local row
    const int c4  = (tid & 7) << 2;    // 0,4,...,28  local col group (4 cols)
    const bool diag = (bi == bj);

    const int n4 = n >> 2;
    const int n2 = n >> 1;

    // --- issue ALL global loads up front (independent of smem) ---
    const int rowP  = bi * TILE + lr;
    const int colP0 = bj * TILE + c4;
    float4 eP  = edgep4[(long)rowP * n4 + (colP0 >> 2)];
    long gPi   = (long)rowP * n2 + (colP0 >> 1);
    float4 gP0 = gedge4[gPi];
    float4 gP1 = gedge4[gPi + 1];

    const int rowQ  = bj * TILE + lr;
    const int colQ0 = bi * TILE + c4;
    float4 eQ, gQ0, gQ1;
    if (!diag) {
        eQ  = edgep4[(long)rowQ * n4 + (colQ0 >> 2)];
        long gQi = (long)rowQ * n2 + (colQ0 >> 1);
        gQ0 = gedge4[gQi];
        gQ1 = gedge4[gQi + 1];
    }

    __shared__ float vP[TILE][TILE + 1];
    __shared__ float nrI[TILE];   // not_root for bi-tile (cols of Q)
    __shared__ float nrJ[TILE];   // not_root for bj-tile (cols of P)

    if (tid < 2 * TILE) {
        int local = tid & (TILE - 1);
        int base  = (tid < TILE) ? bi : bj;
        int g     = base * TILE + local;
        float p   = rootp[g];
        float2 gr = groot[g];
        float nr  = ((p + gr.x) > (1.0f - p + gr.y)) ? 0.0f : 1.0f;
        if (tid < TILE) nrI[local] = nr; else nrJ[local] = nr;
    }
    __syncthreads();

    // --- Phase A: v = b * nr[col] for tile P(bi,bj) ---
    float v0 = (((eP.x + gP0.x) > (1.0f - eP.x + gP0.y)) ? 1.0f : 0.0f) * nrJ[c4 + 0];
    float v1 = (((eP.y + gP0.z) > (1.0f - eP.y + gP0.w)) ? 1.0f : 0.0f) * nrJ[c4 + 1];
    float v2 = (((eP.z + gP1.x) > (1.0f - eP.z + gP1.y)) ? 1.0f : 0.0f) * nrJ[c4 + 2];
    float v3 = (((eP.w + gP1.z) > (1.0f - eP.w + gP1.w)) ? 1.0f : 0.0f) * nrJ[c4 + 3];
    vP[lr][c4 + 0] = v0;
    vP[lr][c4 + 1] = v1;
    vP[lr][c4 + 2] = v2;
    vP[lr][c4 + 3] = v3;

    if (!diag) {
        // P strictly above diagonal: dag = v directly (store before sync).
        out4[(long)rowP * n4 + (colP0 >> 2)] = make_float4(v0, v1, v2, v3);

        float q0 = (((eQ.x + gQ0.x) > (1.0f - eQ.x + gQ0.y)) ? 1.0f : 0.0f) * nrI[c4 + 0];
        float q1 = (((eQ.y + gQ0.z) > (1.0f - eQ.y + gQ0.w)) ? 1.0f : 0.0f) * nrI[c4 + 1];
        float q2 = (((eQ.z + gQ1.x) > (1.0f - eQ.z + gQ1.y)) ? 1.0f : 0.0f) * nrI[c4 + 2];
        float q3 = (((eQ.w + gQ1.z) > (1.0f - eQ.w + gQ1.w)) ? 1.0f : 0.0f) * nrI[c4 + 3];

        __syncthreads();

        // Q below diagonal: dag = vQ * (1 - vP^T)
        float o0 = q0 * (1.0f - vP[c4 + 0][lr]);
        float o1 = q1 * (1.0f - vP[c4 + 1][lr]);
        float o2 = q2 * (1.0f - vP[c4 + 2][lr]);
        float o3 = q3 * (1.0f - vP[c4 + 3][lr]);
        out4[(long)rowQ * n4 + (colQ0 >> 2)] = make_float4(o0, o1, o2, o3);
    } else {
        __syncthreads();
        // Diagonal tile: both triangles + zero diagonal.
        float o[4] = {v0, v1, v2, v3};
        #pragma unroll
        for (int k = 0; k < 4; k++) {
            int cc = c4 + k;
            if (cc < lr)       o[k] = o[k] * (1.0f - vP[cc][lr]);
            else if (cc == lr) o[k] = 0.0f;
            // cc > lr: keep v
        }
        out4[(long)rowP * n4 + (colP0 >> 2)] = make_float4(o[0], o[1], o[2], o[3]);
    }
}

extern "C" void kernel_launch(void* const* d_in, const int* in_sizes, int n_in,
                              void* d_out, int out_size) {
    const float*  rootp  = (const float*)d_in[0];
    const float4* edgep4 = (const float4*)d_in[1];
    const float2* groot  = (const float2*)d_in[2];
    const float4* gedge4 = (const float4*)d_in[3];
    float4* out = (float4*)d_out;
    int n = in_sizes[0];
    int T = n / TILE;
    int nblk = T * (T + 1) / 2;

    dag_pair_kernel<<<nblk, 256>>>(rootp, edgep4, groot, gedge4, out, n, T);
}